// round 1
// baseline (speedup 1.0000x reference)
#include <cuda_runtime.h>
#include <math.h>

#define BB 24
#define SS 512
#define DD 512
#define HH 8
#define DKH 64
#define DFF 2048
#define NLAY 6
#define FC1D 512
#define FC2D 256
#define NTOK (BB*SS)
#define HR 7   /* H - HS routed heads */

// ------------------------- scratch (device globals) -------------------------
__device__ float g_qemb[NTOK*DD];
__device__ float g_x[NTOK*DD];
__device__ float g_y[NTOK*DD];
__device__ float g_ql[NTOK*DD];
__device__ float g_vl[NTOK*DD];
__device__ float g_ctx[NTOK*DD];
__device__ float g_att[NTOK*DD];
__device__ float g_x1[NTOK*DD];
__device__ float g_ff[NTOK*DFF];
__device__ float g_sc[(size_t)BB*HH*SS*SS];
__device__ float g_dyn[NTOK*HR];
__device__ float g_rmask[BB*HH];
__device__ float g_hcat[NTOK*2*DD];
__device__ float g_h1[NTOK*FC1D];
__device__ float g_h2[NTOK*FC2D];

// ------------------------- embeddings -------------------------
__global__ void embed_kernel(const int* __restrict__ qd, const int* __restrict__ tg,
                             const int* __restrict__ pid,
                             const float* __restrict__ qtab, const float* __restrict__ qatab,
                             const float* __restrict__ qdtab, const float* __restrict__ qadtab,
                             const float* __restrict__ pdtab) {
    int t = blockIdx.x;
    int d = threadIdx.x;                 // blockDim = 512
    int qi = qd[t], ti = tg[t], pi = pid[t];
    float ps  = pdtab[pi];
    float qe  = qtab[(size_t)qi*DD + d];
    float qdv = qdtab[(size_t)qi*DD + d];
    float qemb = qe + ps * qdv;
    float qae  = qatab[(size_t)ti*DD + d] + qe + ps * (qadtab[(size_t)ti*DD + d] + qdv);
    g_qemb[(size_t)t*DD + d] = qemb;
    g_x[(size_t)t*DD + d]    = qemb;
    g_y[(size_t)t*DD + d]    = qae;
}

// ------------------------- generic SGEMM: C = A[M,K] @ B[K,N] + bias (+relu) -------------------------
__global__ __launch_bounds__(256) void sgemm(const float* __restrict__ A, const float* __restrict__ B,
                                             const float* __restrict__ bias, float* __restrict__ C,
                                             int M, int N, int K, int relu) {
    __shared__ float As[16][65];   // [k][m]
    __shared__ float Bs[16][64];   // [k][n]
    int tid = threadIdx.x;
    int tx = tid & 15, ty = tid >> 4;
    int m0 = blockIdx.y * 64, n0 = blockIdx.x * 64;
    float acc[4][4] = {};
    for (int k0 = 0; k0 < K; k0 += 16) {
        #pragma unroll
        for (int l = 0; l < 4; l++) {
            int idx = tid + l * 256;
            int r = idx >> 4, c = idx & 15;
            As[c][r] = A[(size_t)(m0 + r) * K + k0 + c];
        }
        #pragma unroll
        for (int l = 0; l < 4; l++) {
            int idx = tid + l * 256;
            int r = idx >> 6, c = idx & 63;
            Bs[r][c] = B[(size_t)(k0 + r) * N + n0 + c];
        }
        __syncthreads();
        #pragma unroll
        for (int kk = 0; kk < 16; kk++) {
            float a[4], b[4];
            #pragma unroll
            for (int i = 0; i < 4; i++) a[i] = As[kk][ty * 4 + i];
            #pragma unroll
            for (int j = 0; j < 4; j++) b[j] = Bs[kk][tx * 4 + j];
            #pragma unroll
            for (int i = 0; i < 4; i++)
                #pragma unroll
                for (int j = 0; j < 4; j++)
                    acc[i][j] += a[i] * b[j];
        }
        __syncthreads();
    }
    #pragma unroll
    for (int i = 0; i < 4; i++) {
        int m = m0 + ty * 4 + i;
        #pragma unroll
        for (int j = 0; j < 4; j++) {
            int n = n0 + tx * 4 + j;
            float v = acc[i][j] + bias[n];
            if (relu) v = fmaxf(v, 0.0f);
            C[(size_t)m * N + n] = v;
        }
    }
}

// ------------------------- attention scores: S[b,h] = Q_h @ Q_h^T / 8 -------------------------
__global__ __launch_bounds__(256) void scores_kernel(const float* __restrict__ ql) {
    int bh = blockIdx.z; int b = bh >> 3; int h = bh & 7;
    const float* Q = ql + (size_t)b * SS * DD + h * DKH;
    int i0 = blockIdx.y * 64, j0 = blockIdx.x * 64;
    __shared__ float Qi[64][65];   // [k][m]
    __shared__ float Qj[64][65];   // [k][n]
    int tid = threadIdx.x;
    int tx = tid & 15, ty = tid >> 4;
    #pragma unroll
    for (int l = 0; l < 16; l++) {
        int idx = tid + l * 256;
        int m = idx >> 6, k = idx & 63;
        Qi[k][m] = Q[(size_t)(i0 + m) * DD + k];
        Qj[k][m] = Q[(size_t)(j0 + m) * DD + k];
    }
    __syncthreads();
    float acc[4][4] = {};
    #pragma unroll 8
    for (int k = 0; k < 64; k++) {
        float a[4], bb[4];
        #pragma unroll
        for (int i = 0; i < 4; i++) a[i] = Qi[k][ty * 4 + i];
        #pragma unroll
        for (int j = 0; j < 4; j++) bb[j] = Qj[k][tx * 4 + j];
        #pragma unroll
        for (int i = 0; i < 4; i++)
            #pragma unroll
            for (int j = 0; j < 4; j++)
                acc[i][j] += a[i] * bb[j];
    }
    float* out = g_sc + (size_t)bh * SS * SS;
    #pragma unroll
    for (int i = 0; i < 4; i++)
        #pragma unroll
        for (int j = 0; j < 4; j++)
            out[(size_t)(i0 + ty * 4 + i) * SS + (j0 + tx * 4 + j)] = acc[i][j] * 0.125f;
}

// ------------------------- masked softmax over score rows (in place) -------------------------
__global__ __launch_bounds__(256) void attn_softmax(int strict) {
    int gid = blockIdx.x;           // (b*H + h)*S + i
    int i = gid & (SS - 1);
    float* row = g_sc + (size_t)gid * SS;
    int tid = threadIdx.x;
    __shared__ float red[256];
    float l0, l1;
    int j0 = tid, j1 = tid + 256;
    if (i == 0) { l0 = 0.0f; l1 = 0.0f; }
    else {
        bool a0 = strict ? (j0 < i) : (j0 <= i);
        bool a1 = strict ? (j1 < i) : (j1 <= i);
        l0 = a0 ? row[j0] : -1e9f;
        l1 = a1 ? row[j1] : -1e9f;
    }
    // max reduce
    red[tid] = fmaxf(l0, l1); __syncthreads();
    for (int s = 128; s; s >>= 1) { if (tid < s) red[tid] = fmaxf(red[tid], red[tid + s]); __syncthreads(); }
    float mx = red[0]; __syncthreads();
    float e0 = expf(l0 - mx), e1 = expf(l1 - mx);
    red[tid] = e0 + e1; __syncthreads();
    for (int s = 128; s; s >>= 1) { if (tid < s) red[tid] += red[tid + s]; __syncthreads(); }
    float inv = 1.0f / red[0];
    row[j0] = e0 * inv;
    row[j1] = e1 * inv;
}

// ------------------------- ctx: (attn @ V) * rmask -------------------------
__global__ __launch_bounds__(256) void ctx_kernel(const float* __restrict__ vl) {
    int bh = blockIdx.z; int b = bh >> 3; int h = bh & 7;
    const float* Am = g_sc + (size_t)bh * SS * SS;           // [S,S]
    const float* V  = vl + (size_t)b * SS * DD + h * DKH;    // ldb = DD, 64 cols
    float rm = g_rmask[bh];
    int m0 = blockIdx.y * 64;
    __shared__ float As[16][65];
    __shared__ float Bs[16][64];
    int tid = threadIdx.x;
    int tx = tid & 15, ty = tid >> 4;
    float acc[4][4] = {};
    for (int k0 = 0; k0 < SS; k0 += 16) {
        #pragma unroll
        for (int l = 0; l < 4; l++) {
            int idx = tid + l * 256;
            int r = idx >> 4, c = idx & 15;
            As[c][r] = Am[(size_t)(m0 + r) * SS + k0 + c];
        }
        #pragma unroll
        for (int l = 0; l < 4; l++) {
            int idx = tid + l * 256;
            int r = idx >> 6, c = idx & 63;
            Bs[r][c] = V[(size_t)(k0 + r) * DD + c];
        }
        __syncthreads();
        #pragma unroll
        for (int kk = 0; kk < 16; kk++) {
            float a[4], bb[4];
            #pragma unroll
            for (int i = 0; i < 4; i++) a[i] = As[kk][ty * 4 + i];
            #pragma unroll
            for (int j = 0; j < 4; j++) bb[j] = Bs[kk][tx * 4 + j];
            #pragma unroll
            for (int i = 0; i < 4; i++)
                #pragma unroll
                for (int j = 0; j < 4; j++)
                    acc[i][j] += a[i] * bb[j];
        }
        __syncthreads();
    }
    #pragma unroll
    for (int i = 0; i < 4; i++) {
        int tok = b * SS + m0 + ty * 4 + i;
        #pragma unroll
        for (int j = 0; j < 4; j++)
            g_ctx[(size_t)tok * DD + h * DKH + tx * 4 + j] = acc[i][j] * rm;
    }
}

// ------------------------- router: gates=softmax(ql@Wg), top2 -> dyn scores -------------------------
__global__ void router_kernel(const float* __restrict__ Wg) {
    int warp = (blockIdx.x * blockDim.x + threadIdx.x) >> 5;
    int lane = threadIdx.x & 31;
    if (warp >= NTOK) return;
    const float* xrow = g_ql + (size_t)warp * DD;
    float acc[HR];
    #pragma unroll
    for (int o = 0; o < HR; o++) acc[o] = 0.0f;
    #pragma unroll 4
    for (int c = 0; c < 16; c++) {
        int k = c * 32 + lane;
        float a = xrow[k];
        #pragma unroll
        for (int o = 0; o < HR; o++) acc[o] += a * Wg[k * HR + o];
    }
    #pragma unroll
    for (int o = 0; o < HR; o++)
        #pragma unroll
        for (int off = 16; off; off >>= 1)
            acc[o] += __shfl_xor_sync(0xffffffffu, acc[o], off);
    // softmax over 7 (all lanes redundantly)
    float mx = acc[0];
    #pragma unroll
    for (int o = 1; o < HR; o++) mx = fmaxf(mx, acc[o]);
    float g[HR], s = 0.0f;
    #pragma unroll
    for (int o = 0; o < HR; o++) { g[o] = expf(acc[o] - mx); s += g[o]; }
    float inv = 1.0f / s;
    #pragma unroll
    for (int o = 0; o < HR; o++) g[o] *= inv;
    // top-2 (ties -> lower index, matches lax.top_k)
    int i1 = 0;
    #pragma unroll
    for (int o = 1; o < HR; o++) if (g[o] > g[i1]) i1 = o;
    int i2 = (i1 == 0) ? 1 : 0;
    #pragma unroll
    for (int o = 0; o < HR; o++) if (o != i1 && o != i2 && g[o] > g[i2]) i2 = o;
    if (lane < HR)
        g_dyn[(size_t)warp * HR + lane] = (lane == i1 || lane == i2) ? g[lane] : 0.0f;
}

// ------------------------- rmask = concat(1, mean_s(dyn)) -------------------------
__global__ void rmask_kernel() {
    int b = blockIdx.x / HR, o = blockIdx.x % HR;
    __shared__ float red[256];
    int tid = threadIdx.x;
    float s = 0.0f;
    for (int si = tid; si < SS; si += 256)
        s += g_dyn[((size_t)b * SS + si) * HR + o];
    red[tid] = s; __syncthreads();
    for (int st = 128; st; st >>= 1) { if (tid < st) red[tid] += red[tid + st]; __syncthreads(); }
    if (tid == 0) {
        g_rmask[b * HH + 1 + o] = red[0] * (1.0f / SS);
        if (o == 0) g_rmask[b * HH] = 1.0f;
    }
}

// ------------------------- fused residual add + layernorm -------------------------
__global__ __launch_bounds__(256) void add_ln(const float* __restrict__ X, const float* __restrict__ A,
                                              const float* __restrict__ gam, const float* __restrict__ bet,
                                              float* __restrict__ out) {
    int t = blockIdx.x;
    int tid = threadIdx.x;
    __shared__ float red[256];
    float v0 = X[(size_t)t*DD + tid]       + A[(size_t)t*DD + tid];
    float v1 = X[(size_t)t*DD + tid + 256] + A[(size_t)t*DD + tid + 256];
    red[tid] = v0 + v1; __syncthreads();
    for (int s = 128; s; s >>= 1) { if (tid < s) red[tid] += red[tid + s]; __syncthreads(); }
    float mean = red[0] * (1.0f / DD); __syncthreads();
    float d0 = v0 - mean, d1 = v1 - mean;
    red[tid] = d0 * d0 + d1 * d1; __syncthreads();
    for (int s = 128; s; s >>= 1) { if (tid < s) red[tid] += red[tid + s]; __syncthreads(); }
    float inv = rsqrtf(red[0] * (1.0f / DD) + 1e-5f);
    out[(size_t)t*DD + tid]       = d0 * inv * gam[tid]       + bet[tid];
    out[(size_t)t*DD + tid + 256] = d1 * inv * gam[tid + 256] + bet[tid + 256];
}

// ------------------------- output-head helpers -------------------------
__global__ void concat_kernel() {
    int t = blockIdx.x, d = threadIdx.x;     // blockDim = 512
    g_hcat[(size_t)t * 1024 + d]       = g_x[(size_t)t * DD + d];
    g_hcat[(size_t)t * 1024 + 512 + d] = g_qemb[(size_t)t * DD + d];
}

__global__ void final_kernel(const float* __restrict__ ow3, const float* __restrict__ ob3,
                             float* __restrict__ out) {
    int warp = (blockIdx.x * blockDim.x + threadIdx.x) >> 5;
    int lane = threadIdx.x & 31;
    if (warp >= NTOK) return;
    float s = 0.0f;
    #pragma unroll
    for (int c = 0; c < 8; c++) {
        int k = c * 32 + lane;
        s += g_h2[(size_t)warp * FC2D + k] * ow3[k];
    }
    #pragma unroll
    for (int off = 16; off; off >>= 1) s += __shfl_xor_sync(0xffffffffu, s, off);
    if (lane == 0) {
        float z = s + ob3[0];
        out[warp] = 1.0f / (1.0f + expf(-z));
    }
}

// ------------------------- host orchestration -------------------------
struct Ptrs {
    float *qemb, *x, *y, *ql, *vl, *ctx, *att, *x1, *ff, *hcat, *h1, *h2;
};

static void run_block(const Ptrs& P, float* xq, const float* xv, int strict, int layer,
                      const float* Wq, const float* bq, const float* Wv, const float* bv,
                      const float* Wg, const float* Wo, const float* bo,
                      const float* ln1g, const float* ln1b,
                      const float* W1, const float* b1, const float* W2, const float* b2,
                      const float* ln2g, const float* ln2b) {
    const float* wq = Wq + (size_t)layer * DD * DD;
    const float* wv = Wv + (size_t)layer * DD * DD;
    const float* wg = Wg + (size_t)layer * DD * HR;
    const float* wo = Wo + (size_t)layer * DD * DD;
    const float* w1 = W1 + (size_t)layer * DD * DFF;
    const float* w2 = W2 + (size_t)layer * DFF * DD;
    const float* pbq = bq + (size_t)layer * DD;
    const float* pbv = bv + (size_t)layer * DD;
    const float* pbo = bo + (size_t)layer * DD;
    const float* pb1 = b1 + (size_t)layer * DFF;
    const float* pb2 = b2 + (size_t)layer * DD;
    const float* g1 = ln1g + (size_t)layer * DD; const float* be1 = ln1b + (size_t)layer * DD;
    const float* g2 = ln2g + (size_t)layer * DD; const float* be2 = ln2b + (size_t)layer * DD;

    dim3 gproj(DD / 64, NTOK / 64);
    sgemm<<<gproj, 256>>>(xq, wq, pbq, P.ql, NTOK, DD, DD, 0);
    sgemm<<<gproj, 256>>>(xv, wv, pbv, P.vl, NTOK, DD, DD, 0);
    router_kernel<<<NTOK / 4, 128>>>(wg);
    rmask_kernel<<<BB * HR, 256>>>();
    scores_kernel<<<dim3(SS / 64, SS / 64, BB * HH), 256>>>(P.ql);
    attn_softmax<<<BB * HH * SS, 256>>>(strict);
    ctx_kernel<<<dim3(1, SS / 64, BB * HH), 256>>>(P.vl);
    sgemm<<<gproj, 256>>>(P.ctx, wo, pbo, P.att, NTOK, DD, DD, 0);
    add_ln<<<NTOK, 256>>>(xq, P.att, g1, be1, P.x1);
    sgemm<<<dim3(DFF / 64, NTOK / 64), 256>>>(P.x1, w1, pb1, P.ff, NTOK, DFF, DD, 1);
    sgemm<<<gproj, 256>>>(P.ff, w2, pb2, P.att, NTOK, DD, DFF, 0);
    add_ln<<<NTOK, 256>>>(P.x1, P.att, g2, be2, xq);   // write result back into xq buffer
}

extern "C" void kernel_launch(void* const* d_in, const int* in_sizes, int n_in,
                              void* d_out, int out_size) {
    const int*   q_data    = (const int*)d_in[0];
    const int*   target    = (const int*)d_in[1];
    const int*   pid_data  = (const int*)d_in[2];
    const float* q_embed   = (const float*)d_in[3];
    const float* qa_embed  = (const float*)d_in[4];
    const float* q_diff    = (const float*)d_in[5];
    const float* qa_diff   = (const float*)d_in[6];
    const float* pid_diff  = (const float*)d_in[7];
    const float* Wq = (const float*)d_in[8];   const float* bq = (const float*)d_in[9];
    const float* Wv = (const float*)d_in[10];  const float* bv = (const float*)d_in[11];
    const float* Wg = (const float*)d_in[12];
    const float* Wo = (const float*)d_in[13];  const float* bo = (const float*)d_in[14];
    const float* ln1g = (const float*)d_in[15]; const float* ln1b = (const float*)d_in[16];
    const float* W1 = (const float*)d_in[17];  const float* b1 = (const float*)d_in[18];
    const float* W2 = (const float*)d_in[19];  const float* b2 = (const float*)d_in[20];
    const float* ln2g = (const float*)d_in[21]; const float* ln2b = (const float*)d_in[22];
    const float* ow1 = (const float*)d_in[23]; const float* ob1 = (const float*)d_in[24];
    const float* ow2 = (const float*)d_in[25]; const float* ob2 = (const float*)d_in[26];
    const float* ow3 = (const float*)d_in[27]; const float* ob3 = (const float*)d_in[28];
    float* out = (float*)d_out;

    Ptrs P;
    void* p;
    cudaGetSymbolAddress(&p, g_qemb); P.qemb = (float*)p;
    cudaGetSymbolAddress(&p, g_x);    P.x    = (float*)p;
    cudaGetSymbolAddress(&p, g_y);    P.y    = (float*)p;
    cudaGetSymbolAddress(&p, g_ql);   P.ql   = (float*)p;
    cudaGetSymbolAddress(&p, g_vl);   P.vl   = (float*)p;
    cudaGetSymbolAddress(&p, g_ctx);  P.ctx  = (float*)p;
    cudaGetSymbolAddress(&p, g_att);  P.att  = (float*)p;
    cudaGetSymbolAddress(&p, g_x1);   P.x1   = (float*)p;
    cudaGetSymbolAddress(&p, g_ff);   P.ff   = (float*)p;
    cudaGetSymbolAddress(&p, g_hcat); P.hcat = (float*)p;
    cudaGetSymbolAddress(&p, g_h1);   P.h1   = (float*)p;
    cudaGetSymbolAddress(&p, g_h2);   P.h2   = (float*)p;

    embed_kernel<<<NTOK, 512>>>(q_data, target, pid_data, q_embed, qa_embed,
                                q_diff, qa_diff, pid_diff);

    // blocks_1: y = block(y, y, strict=False), layers 0..NB-1
    run_block(P, P.y, P.y, 0, 0, Wq, bq, Wv, bv, Wg, Wo, bo, ln1g, ln1b, W1, b1, W2, b2, ln2g, ln2b);
    run_block(P, P.y, P.y, 0, 1, Wq, bq, Wv, bv, Wg, Wo, bo, ln1g, ln1b, W1, b1, W2, b2, ln2g, ln2b);
    // blocks_2: alternate self (non-strict) / cross-with-y (strict), layers 2..5
    run_block(P, P.x, P.x, 0, 2, Wq, bq, Wv, bv, Wg, Wo, bo, ln1g, ln1b, W1, b1, W2, b2, ln2g, ln2b);
    run_block(P, P.x, P.y, 1, 3, Wq, bq, Wv, bv, Wg, Wo, bo, ln1g, ln1b, W1, b1, W2, b2, ln2g, ln2b);
    run_block(P, P.x, P.x, 0, 4, Wq, bq, Wv, bv, Wg, Wo, bo, ln1g, ln1b, W1, b1, W2, b2, ln2g, ln2b);
    run_block(P, P.x, P.y, 1, 5, Wq, bq, Wv, bv, Wg, Wo, bo, ln1g, ln1b, W1, b1, W2, b2, ln2g, ln2b);

    // output head
    concat_kernel<<<NTOK, 512>>>();
    sgemm<<<dim3(FC1D / 64, NTOK / 64), 256>>>(P.hcat, ow1, ob1, P.h1, NTOK, FC1D, 2 * DD, 1);
    sgemm<<<dim3(FC2D / 64, NTOK / 64), 256>>>(P.h1, ow2, ob2, P.h2, NTOK, FC2D, FC1D, 1);
    final_kernel<<<NTOK / 4, 128>>>(ow3, ob3, out);
}